// round 4
// baseline (speedup 1.0000x reference)
#include <cuda_runtime.h>
#include <cstdint>

#define HH 1536
#define WW 2048
#define NN (HH*WW)
#define WSHIFT 11
#define WMASK 2047

// scratch (device globals: allocation-free rule)
__device__ unsigned char g_mask[NN];   // bit0: comb, bit1: text
__device__ int g_parent[NN];           // union-find parent; -1 = background
__device__ int g_xmin[NN];
__device__ int g_xmax[NN];
__device__ int g_ymax[NN];
__device__ int g_tflag[NN];

// ---------------- mask: threshold both channels ----------------
__global__ void k_mask(const float* __restrict__ x) {
    int t = blockIdx.x * blockDim.x + threadIdx.x;
    if (t >= NN / 4) return;
    const float4* x4 = (const float4*)x;
    float4 a = x4[2 * t];
    float4 b = x4[2 * t + 1];
    uchar4 m;
    {
        unsigned tt = a.x > 0.4f; unsigned cc = tt | (a.y > 0.4f);
        m.x = (unsigned char)(cc | (tt << 1));
    }
    {
        unsigned tt = a.z > 0.4f; unsigned cc = tt | (a.w > 0.4f);
        m.y = (unsigned char)(cc | (tt << 1));
    }
    {
        unsigned tt = b.x > 0.4f; unsigned cc = tt | (b.y > 0.4f);
        m.z = (unsigned char)(cc | (tt << 1));
    }
    {
        unsigned tt = b.z > 0.4f; unsigned cc = tt | (b.w > 0.4f);
        m.w = (unsigned char)(cc | (tt << 1));
    }
    ((uchar4*)g_mask)[t] = m;
}

// ---------------- tile: dilation (fg) + in-tile CCL + scratch init ----------------
__global__ void __launch_bounds__(1024, 1) k_tile() {
    __shared__ unsigned char sm[34][34];
    __shared__ int lab[1024];
    __shared__ int changed;
    int tx = threadIdx.x, ty = threadIdx.y;
    int lid = ty * 32 + tx;
    int bx = blockIdx.x * 32, by = blockIdx.y * 32;

    // stage 34x34 halo region of comb mask (OOB -> 0, matching init-value pad)
    for (int k = lid; k < 34 * 34; k += 1024) {
        int ly = k / 34, lx = k % 34;
        int gy = by + ly - 1, gx = bx + lx - 1;
        unsigned char v = 0;
        if (gy >= 0 && gy < HH && gx >= 0 && gx < WW) v = g_mask[(gy << WSHIFT) | gx];
        sm[ly][lx] = v;
    }
    __syncthreads();

    // fg = 3x3 dilation of comb
    int fg = 0;
#pragma unroll
    for (int dy = 0; dy < 3; dy++)
#pragma unroll
        for (int dx = 0; dx < 3; dx++)
            fg |= sm[ty + dy][tx + dx] & 1;

    lab[lid] = fg ? lid : 0x7fffffff;
    __syncthreads();

    // min-label propagation with pointer jumping (chaotic relaxation, monotone)
    while (true) {
        if (lid == 0) changed = 0;
        __syncthreads();
        if (fg) {
            int cur = lab[lid];
            int m = cur;
            if (tx > 0)  m = min(m, lab[lid - 1]);
            if (tx < 31) m = min(m, lab[lid + 1]);
            if (ty > 0)  m = min(m, lab[lid - 32]);
            if (ty < 31) m = min(m, lab[lid + 32]);
            m = min(m, lab[m]);
            m = min(m, lab[m]);
            if (m < cur) { lab[lid] = m; changed = 1; }
        }
        __syncthreads();
        if (!changed) break;
        __syncthreads();  // protect the flag read from the next reset
    }

    int gi = ((by + ty) << WSHIFT) | (bx + tx);
    int pv = -1;
    if (fg) {
        int l = lab[lid];
        pv = ((by + (l >> 5)) << WSHIFT) | (bx + (l & 31));
    }
    g_parent[gi] = pv;
    g_xmin[gi] = 0x7fffffff;
    g_xmax[gi] = -1;
    g_ymax[gi] = -1;
    g_tflag[gi] = 0;
}

// ---------------- union-find (links always point to smaller index) ----------------
__device__ __forceinline__ int uf_find(int i) {
    int n;
    while ((n = __ldcg(&g_parent[i])) != i) i = n;
    return i;
}

__device__ __forceinline__ void uf_union(int a, int b) {
    while (true) {
        a = uf_find(a);
        b = uf_find(b);
        if (a == b) return;
        int lo = min(a, b), hi = max(a, b);
        int old = atomicMin(&g_parent[hi], lo);
        if (old == hi) return;
        a = lo; b = old;
    }
}

// merge across tile boundaries only (~200K unions instead of ~6M)
__global__ void k_merge() {
    int i = blockIdx.x * blockDim.x + threadIdx.x;
    if (i >= NN) return;
    if (__ldcg(&g_parent[i]) < 0) return;
    int gx = i & WMASK, gy = i >> WSHIFT;
    if ((gx & 31) == 31 && gx < WW - 1 && __ldcg(&g_parent[i + 1]) >= 0)
        uf_union(i, i + 1);
    if ((gy & 31) == 31 && gy < HH - 1 && __ldcg(&g_parent[i + WW]) >= 0)
        uf_union(i, i + WW);
}

__global__ void k_flatten() {
    int i = blockIdx.x * blockDim.x + threadIdx.x;
    if (i >= NN) return;
    int p = g_parent[i];
    if (p < 0) return;
    g_parent[i] = uf_find(p);
}

// ---------------- per-component reductions (warp-aggregated + checked atomics) ----------------
__global__ void k_reduce() {
    int i = blockIdx.x * blockDim.x + threadIdx.x;   // grid is exact multiple of 256
    int r = g_parent[i];
    int col = i & WMASK;
    int row = i >> WSHIFT;
    unsigned text = (r >= 0) ? (unsigned)((g_mask[i] >> 1) & 1u) : 0u;

    unsigned peers = __match_any_sync(0xffffffffu, r);
    int cmin = __reduce_min_sync(peers, col);
    int cmax = __reduce_max_sync(peers, col);
    unsigned tor = __reduce_or_sync(peers, text);
    int lane = threadIdx.x & 31;

    if (r >= 0 && lane == (__ffs(peers) - 1)) {
        // monotone values -> stale-read skip is always safe
        if (cmin < __ldcg(&g_xmin[r])) atomicMin(&g_xmin[r], cmin);
        if (cmax > __ldcg(&g_xmax[r])) atomicMax(&g_xmax[r], cmax);
        if (row  > __ldcg(&g_ymax[r])) atomicMax(&g_ymax[r], row);
        if (tor && __ldcg(&g_tflag[r]) == 0) g_tflag[r] = 1;
    }
}

// ---------------- output (float32: harness output dtype) ----------------
__global__ void k_zero4(float* __restrict__ out, int n4) {
    int i = blockIdx.x * blockDim.x + threadIdx.x;
    if (i < n4) ((float4*)out)[i] = make_float4(0.f, 0.f, 0.f, 0.f);
}

__global__ void k_zero1(float* __restrict__ out, int base, int n) {
    int i = blockIdx.x * blockDim.x + threadIdx.x;
    if (i < n) out[base + i] = 0.f;
}

__global__ void k_out(float* __restrict__ out) {
    int i = blockIdx.x * blockDim.x + threadIdx.x;
    if (i >= NN) return;
    if (g_parent[i] != i) return;          // component root (implies fg)
    int ymin = i >> WSHIFT;                // root = min flat index -> its row IS ymin
    int xmin = g_xmin[i];
    int h = g_ymax[i] - ymin;
    int w = g_xmax[i] - xmin;
    if (h > 4 && w > 4 && g_tflag[i]) {
        // bboxes[i] = {ymin,xmin,h,w} as float32
        ((float4*)out)[i] = make_float4((float)ymin, (float)xmin, (float)h, (float)w);
        out[4 * NN + i] = 1.0f;            // valid[i]
    }
}

extern "C" void kernel_launch(void* const* d_in, const int* in_sizes, int n_in,
                              void* d_out, int out_size) {
    const float* x = (const float*)d_in[0];
    float* out = (float*)d_out;

    k_mask<<<(NN / 4 + 255) / 256, 256>>>(x);

    dim3 bt(32, 32), gt(WW / 32, HH / 32);
    k_tile<<<gt, bt>>>();

    k_merge<<<NN / 256, 256>>>();
    k_flatten<<<NN / 256, 256>>>();

    int n4 = out_size / 4;
    if (n4 > 0) k_zero4<<<(n4 + 255) / 256, 256>>>(out, n4);
    int rem = out_size - n4 * 4;
    if (rem > 0) k_zero1<<<1, 256>>>(out, n4 * 4, rem);

    k_reduce<<<NN / 256, 256>>>();
    k_out<<<NN / 256, 256>>>(out);
}